// round 9
// baseline (speedup 1.0000x reference)
#include <cuda_runtime.h>
#include <cuda_bf16.h>
#include <cstdint>

#define EDIM 1024
#define BDIM 1024
#define G4   4096
#define MAXT 16
#define OUTD 34

#define BM 128
#define BN 256
#define BK 64
#define NCK (EDIM / BK)        // 16 k-chunks
#define NTHREADS 512

#define BSTAGE 65536           // Bhi 32K + Blo 32K
#define BHI 0
#define BLO 32768
#define SMEM_LSTM (1024 + 3 * BSTAGE)   // bias + 3 B stages = 197632

#define HSZ (BDIM * EDIM)

// ----------------- device scratch -----------------
__device__ __nv_bfloat16 g_Ws_hi[G4 * EDIM];
__device__ __nv_bfloat16 g_Ws_lo[G4 * EDIM];
__device__ __nv_bfloat16 g_Wh_hi[G4 * EDIM];
__device__ __nv_bfloat16 g_Wh_lo[G4 * EDIM];
__device__ float         g_bsum_p[G4];
// ping-pong h buffers: step t reads parity t&1, writes parity (t+1)&1.
__device__ __nv_bfloat16 g_hhi[2 * HSZ];
__device__ __nv_bfloat16 g_hlo[2 * HSZ];
__device__ float         g_c[HSZ];
__device__ float         g_hseq[MAXT * HSZ];

// ----------------- helpers -----------------
__device__ __forceinline__ uint32_t smem_u32(const void* p) {
    uint32_t a;
    asm("{ .reg .u64 t; cvta.to.shared.u64 t, %1; cvt.u32.u64 %0, t; }" : "=r"(a) : "l"(p));
    return a;
}
__device__ __forceinline__ void cpa16(uint32_t dst, const void* src) {
    asm volatile("cp.async.cg.shared.global [%0], [%1], 16;" :: "r"(dst), "l"(src));
}
__device__ __forceinline__ void cpa_commit() {
    asm volatile("cp.async.commit_group;" ::: "memory");
}
__device__ __forceinline__ void ldsm4(uint32_t* r, uint32_t a) {
    asm volatile("ldmatrix.sync.aligned.m8n8.x4.shared.b16 {%0,%1,%2,%3}, [%4];"
                 : "=r"(r[0]), "=r"(r[1]), "=r"(r[2]), "=r"(r[3]) : "r"(a));
}
__device__ __forceinline__ void mma16816(float* d,
                                         const uint32_t* a,
                                         uint32_t b0, uint32_t b1) {
    asm volatile("mma.sync.aligned.m16n8k16.row.col.f32.bf16.bf16.f32 "
                 "{%0,%1,%2,%3}, {%4,%5,%6,%7}, {%8,%9}, {%0,%1,%2,%3};"
                 : "+f"(d[0]), "+f"(d[1]), "+f"(d[2]), "+f"(d[3])
                 : "r"(a[0]), "r"(a[1]), "r"(a[2]), "r"(a[3]), "r"(b0), "r"(b1));
}
__device__ __forceinline__ uint32_t ldg32(const __nv_bfloat16* p) {
    return *reinterpret_cast<const uint32_t*>(p);
}
__device__ __forceinline__ float fsig(float x) {
    float t = __expf(-x);
    return __fdividef(1.f, 1.f + t);
}
__device__ __forceinline__ float ftanh_(float x) {
    float t = __expf(-2.f * x);
    return __fdividef(1.f - t, 1.f + t);
}
__device__ __forceinline__ void bsplit(float v, unsigned short& h, unsigned short& l) {
    __nv_bfloat16 hb = __float2bfloat16(v);
    float r = v - __bfloat162float(hb);
    __nv_bfloat16 lb = __float2bfloat16(r);
    h = __bfloat16_as_ushort(hb);
    l = __bfloat16_as_ushort(lb);
}

// permutation: original W row r = g*1024 + e  ->  rp = (e>>6)*256 + g*64 + (e&63)

// ----------------- prep kernels -----------------
__global__ void prep_w(const float* __restrict__ Wih, const float* __restrict__ Whh) {
    int id = blockIdx.x * 256 + threadIdx.x;
    int r = id >> 8;
    int q = id & 255;
    float4 a = reinterpret_cast<const float4*>(Wih)[(size_t)r * 256 + q];
    float4 b = reinterpret_cast<const float4*>(Whh)[(size_t)r * 256 + q];
    int g = r >> 10, e = r & 1023;
    int rp = ((e >> 6) << 8) + (g << 6) + (e & 63);
    size_t o = (size_t)rp * 256 + q;

    ushort4 hh, hl, sh, sl;
    bsplit(b.x, hh.x, hl.x); bsplit(b.y, hh.y, hl.y);
    bsplit(b.z, hh.z, hl.z); bsplit(b.w, hh.w, hl.w);
    float4 s = make_float4(a.x + b.x, a.y + b.y, a.z + b.z, a.w + b.w);
    bsplit(s.x, sh.x, sl.x); bsplit(s.y, sh.y, sl.y);
    bsplit(s.z, sh.z, sl.z); bsplit(s.w, sh.w, sl.w);

    reinterpret_cast<ushort4*>(g_Wh_hi)[o] = hh;
    reinterpret_cast<ushort4*>(g_Wh_lo)[o] = hl;
    reinterpret_cast<ushort4*>(g_Ws_hi)[o] = sh;
    reinterpret_cast<ushort4*>(g_Ws_lo)[o] = sl;
}

__global__ void prep_state(const float* __restrict__ h0, const float* __restrict__ c0,
                           const float* __restrict__ bih, const float* __restrict__ bhh) {
    int id = blockIdx.x * 256 + threadIdx.x;
    float4 hv = reinterpret_cast<const float4*>(h0)[id];
    ushort4 hh, hl;
    bsplit(hv.x, hh.x, hl.x); bsplit(hv.y, hh.y, hl.y);
    bsplit(hv.z, hh.z, hl.z); bsplit(hv.w, hh.w, hl.w);
    reinterpret_cast<ushort4*>(g_hhi)[id] = hh;
    reinterpret_cast<ushort4*>(g_hlo)[id] = hl;
    reinterpret_cast<float4*>(g_c)[id] = reinterpret_cast<const float4*>(c0)[id];
    if (id < G4) {
        int g = id >> 10, e = id & 1023;
        int rp = ((e >> 6) << 8) + (g << 6) + (e & 63);
        g_bsum_p[rp] = bih[id] + bhh[id];
    }
}

// ----------------- fused GEMM (mma.sync bf16 3-term) + LSTM update -----------------
__global__ __launch_bounds__(NTHREADS, 1)
void lstm_step(int use_sum, int t) {
    extern __shared__ char smem[];
    float* bias_sm = reinterpret_cast<float*>(smem);
    const uint32_t sbase = smem_u32(smem) + 1024;
    const int tid = threadIdx.x;
    const int lane = tid & 31;
    const int w = tid >> 5;        // 0..15
    const int wm = w & 3;          // m-group (32 rows)
    const int we = w >> 2;         // e-group (16 e-cols)
    const int nb = blockIdx.x;     // 0..15
    const int mb = blockIdx.y;     // 0..7
    const int m0 = mb * BM, n0 = nb * BN;

    // ping-pong: read parity t&1, write parity (t+1)&1
    const __nv_bfloat16* __restrict__ hin_hi = g_hhi + (size_t)(t & 1) * HSZ;
    const __nv_bfloat16* __restrict__ hin_lo = g_hlo + (size_t)(t & 1) * HSZ;
    __nv_bfloat16* __restrict__ hout_hi = g_hhi + (size_t)((t + 1) & 1) * HSZ;
    __nv_bfloat16* __restrict__ hout_lo = g_hlo + (size_t)((t + 1) & 1) * HSZ;

    const __nv_bfloat16* __restrict__ Bh = use_sum ? g_Ws_hi : g_Wh_hi;
    const __nv_bfloat16* __restrict__ Bl = use_sum ? g_Ws_lo : g_Wh_lo;

    if (tid < BN) bias_sm[tid] = g_bsum_p[n0 + tid];

    // ---- B loaders: 8 cp.async per thread per chunk (512 threads, 64KB) ----
    const int lrow = tid >> 3;     // 0..63
    const int lq = tid & 7;

#define LOAD_B(kc)                                                                 \
    {                                                                              \
        if ((kc) < NCK) {                                                          \
            uint32_t sb = sbase + ((kc) % 3) * BSTAGE;                             \
            size_t gc = (size_t)(kc) * 64 + lq * 8;                                \
            _Pragma("unroll")                                                      \
            for (int i = 0; i < 4; ++i) {                                          \
                int row = lrow + i * 64;                                           \
                uint32_t sf = (uint32_t)row * 128 + (((lq ^ (row & 7)) << 4));     \
                cpa16(sb + BHI + sf, Bh + (size_t)(n0 + row) * EDIM + gc);         \
                cpa16(sb + BLO + sf, Bl + (size_t)(n0 + row) * EDIM + gc);         \
            }                                                                      \
        }                                                                          \
        cpa_commit();                                                              \
    }

    // acc[mt][gate][sub][4] : m-tile mt (16 rows), gate, n8 sub-tile
    float acc[2][4][2][4];
#pragma unroll
    for (int i = 0; i < 2; ++i)
#pragma unroll
        for (int j = 0; j < 4; ++j)
#pragma unroll
            for (int s = 0; s < 2; ++s)
#pragma unroll
                for (int k = 0; k < 4; ++k) acc[i][j][s][k] = 0.f;

    // A fragment geometry (LDG direct): rows for this thread
    const int arow = m0 + wm * 32 + (lane >> 2);   // +mt*16, +8 variants
    const int akoff = (lane & 3) * 2;              // k offset within k16
    const __nv_bfloat16* a_hi0 = hin_hi + (size_t)arow * EDIM + akoff;
    const __nv_bfloat16* a_lo0 = hin_lo + (size_t)arow * EDIM + akoff;

    // B ldmatrix lane geometry
    const int bn = (lane & 7) + ((lane >> 4) << 3);
    const int bdq = (lane >> 3) & 1;

    // prologue: 3 chunks in flight (3 commit groups)
    LOAD_B(0)
    LOAD_B(1)
    LOAD_B(2)

    for (int kc = 0; kc < NCK; ++kc) {
        // chunk kc resident when at most 2 newer groups remain in flight
        asm volatile("cp.async.wait_group 2;" ::: "memory");
        __syncthreads();           // chunk kc visible to all warps

        uint32_t sb = sbase + (kc % 3) * BSTAGE;
        const size_t kbase = (size_t)kc * 64;
#pragma unroll
        for (int k16 = 0; k16 < 4; ++k16) {
            int qb = k16 * 2 + bdq;
            uint32_t boffs[4];
#pragma unroll
            for (int g = 0; g < 4; ++g) {
                int br = g * 64 + we * 16 + bn;
                boffs[g] = (uint32_t)br * 128 + ((qb ^ (br & 7)) << 4);
            }
            const size_t k0 = kbase + k16 * 16;
            uint32_t ah[2][4], bf[4][4];
#pragma unroll
            for (int mt = 0; mt < 2; ++mt) {
                const __nv_bfloat16* p = a_hi0 + (size_t)mt * 16 * EDIM + k0;
                ah[mt][0] = ldg32(p);
                ah[mt][1] = ldg32(p + 8 * EDIM);
                ah[mt][2] = ldg32(p + 8);
                ah[mt][3] = ldg32(p + 8 * EDIM + 8);
            }
#pragma unroll
            for (int g = 0; g < 4; ++g) ldsm4(bf[g], sb + BHI + boffs[g]);
            // pass 1: hi*hi
#pragma unroll
            for (int mt = 0; mt < 2; ++mt)
#pragma unroll
                for (int g = 0; g < 4; ++g) {
                    mma16816(acc[mt][g][0], ah[mt], bf[g][0], bf[g][1]);
                    mma16816(acc[mt][g][1], ah[mt], bf[g][2], bf[g][3]);
                }
            // pass 2: lo*hi
            {
                uint32_t al[2][4];
#pragma unroll
                for (int mt = 0; mt < 2; ++mt) {
                    const __nv_bfloat16* p = a_lo0 + (size_t)mt * 16 * EDIM + k0;
                    al[mt][0] = ldg32(p);
                    al[mt][1] = ldg32(p + 8 * EDIM);
                    al[mt][2] = ldg32(p + 8);
                    al[mt][3] = ldg32(p + 8 * EDIM + 8);
                }
#pragma unroll
                for (int mt = 0; mt < 2; ++mt)
#pragma unroll
                    for (int g = 0; g < 4; ++g) {
                        mma16816(acc[mt][g][0], al[mt], bf[g][0], bf[g][1]);
                        mma16816(acc[mt][g][1], al[mt], bf[g][2], bf[g][3]);
                    }
            }
            // pass 3: hi*lo (reuse bf regs)
#pragma unroll
            for (int g = 0; g < 4; ++g) ldsm4(bf[g], sb + BLO + boffs[g]);
#pragma unroll
            for (int mt = 0; mt < 2; ++mt)
#pragma unroll
                for (int g = 0; g < 4; ++g) {
                    mma16816(acc[mt][g][0], ah[mt], bf[g][0], bf[g][1]);
                    mma16816(acc[mt][g][1], ah[mt], bf[g][2], bf[g][3]);
                }
        }

        __syncthreads();           // all warps done reading stage kc%3
        LOAD_B(kc + 3)             // safe to overwrite freed stage (1 commit, may be empty)
    }

    // ---- fused epilogue: per-thread register LSTM update ----
    const int mbase = m0 + wm * 32 + (lane >> 2);
    const int cp2 = (lane & 3) * 2;
    float* hseq = g_hseq + (size_t)t * HSZ;
#pragma unroll
    for (int mt = 0; mt < 2; ++mt) {
#pragma unroll
        for (int rr = 0; rr < 2; ++rr) {
            int m = mbase + mt * 16 + rr * 8;
#pragma unroll
            for (int sub = 0; sub < 2; ++sub) {
                int el = we * 16 + sub * 8 + cp2;
                float xi0 = acc[mt][0][sub][rr*2+0] + bias_sm[el];
                float xi1 = acc[mt][0][sub][rr*2+1] + bias_sm[el + 1];
                float xf0 = acc[mt][1][sub][rr*2+0] + bias_sm[64 + el];
                float xf1 = acc[mt][1][sub][rr*2+1] + bias_sm[64 + el + 1];
                float xg0 = acc[mt][2][sub][rr*2+0] + bias_sm[128 + el];
                float xg1 = acc[mt][2][sub][rr*2+1] + bias_sm[128 + el + 1];
                float xo0 = acc[mt][3][sub][rr*2+0] + bias_sm[192 + el];
                float xo1 = acc[mt][3][sub][rr*2+1] + bias_sm[192 + el + 1];
                size_t off = (size_t)m * EDIM + nb * 64 + el;
                float2 cold = *reinterpret_cast<const float2*>(g_c + off);
                float cn0 = fsig(xf0) * cold.x + fsig(xi0) * ftanh_(xg0);
                float cn1 = fsig(xf1) * cold.y + fsig(xi1) * ftanh_(xg1);
                float hn0 = fsig(xo0) * ftanh_(cn0);
                float hn1 = fsig(xo1) * ftanh_(cn1);
                *reinterpret_cast<float2*>(g_c + off) = make_float2(cn0, cn1);
                *reinterpret_cast<float2*>(hseq + off) = make_float2(hn0, hn1);
                unsigned short h0, l0, h1, l1;
                bsplit(hn0, h0, l0);
                bsplit(hn1, h1, l1);
                *reinterpret_cast<uint32_t*>(reinterpret_cast<unsigned short*>(hout_hi) + off) =
                    (uint32_t)h0 | ((uint32_t)h1 << 16);
                *reinterpret_cast<uint32_t*>(reinterpret_cast<unsigned short*>(hout_lo) + off) =
                    (uint32_t)l0 | ((uint32_t)l1 << 16);
            }
        }
    }
}

// ----------------- output projection -----------------
#define OPR 16
#define OPSTRIDE 1040
__global__ void out_proj(const float* __restrict__ Wo, const float* __restrict__ bo,
                         float* __restrict__ out, int T) {
    extern __shared__ float hs[];
    int t = blockIdx.y;
    int b0 = blockIdx.x * OPR;
    int tid = threadIdx.y * 17 + threadIdx.x;
    const float4* src = reinterpret_cast<const float4*>(g_hseq + ((size_t)t * BDIM + b0) * EDIM);
    for (int i = tid; i < OPR * 256; i += 136) {
        int r = i >> 8, c = i & 255;
        reinterpret_cast<float4*>(hs + r * OPSTRIDE)[c] = src[(size_t)r * 256 + c];
    }
    __syncthreads();
    int o0 = threadIdx.x * 2, o1 = o0 + 1;
    int r0 = threadIdx.y * 2, r1 = r0 + 1;
    const float4* w0 = reinterpret_cast<const float4*>(Wo + (size_t)o0 * EDIM);
    const float4* w1 = reinterpret_cast<const float4*>(Wo + (size_t)o1 * EDIM);
    const float4* h0 = reinterpret_cast<const float4*>(hs + r0 * OPSTRIDE);
    const float4* h1 = reinterpret_cast<const float4*>(hs + r1 * OPSTRIDE);
    float s00 = 0.f, s01 = 0.f, s10 = 0.f, s11 = 0.f;
#pragma unroll 4
    for (int k = 0; k < 256; ++k) {
        float4 a = h0[k], b = h1[k], x = w0[k], y = w1[k];
        s00 += a.x * x.x + a.y * x.y + a.z * x.z + a.w * x.w;
        s01 += a.x * y.x + a.y * y.y + a.z * y.z + a.w * y.w;
        s10 += b.x * x.x + b.y * x.y + b.z * x.z + b.w * x.w;
        s11 += b.x * y.x + b.y * y.y + b.z * y.z + b.w * y.w;
    }
    float bb0 = bo[o0], bb1 = bo[o1];
    size_t ob = ((size_t)(b0 + r0) * T + t) * OUTD;
    out[ob + o0] = s00 + bb0;
    out[ob + o1] = s01 + bb1;
    ob = ((size_t)(b0 + r1) * T + t) * OUTD;
    out[ob + o0] = s10 + bb0;
    out[ob + o1] = s11 + bb1;
}

// ----------------- launch -----------------
extern "C" void kernel_launch(void* const* d_in, const int* in_sizes, int n_in,
                              void* d_out, int out_size) {
    const float* h     = (const float*)d_in[0];
    const float* c     = (const float*)d_in[1];
    const float* W_ih  = (const float*)d_in[2];
    const float* W_hh  = (const float*)d_in[3];
    const float* b_ih  = (const float*)d_in[4];
    const float* b_hh  = (const float*)d_in[5];
    const float* W_out = (const float*)d_in[6];
    const float* b_out = (const float*)d_in[7];
    float* out = (float*)d_out;

    int T = out_size / (BDIM * OUTD);
    if (T < 1) T = 1;
    if (T > MAXT) T = MAXT;

    cudaFuncSetAttribute(lstm_step, cudaFuncAttributeMaxDynamicSharedMemorySize, SMEM_LSTM);
    cudaFuncSetAttribute(out_proj, cudaFuncAttributeMaxDynamicSharedMemorySize,
                         OPR * OPSTRIDE * 4);

    prep_w<<<G4, 256>>>(W_ih, W_hh);
    prep_state<<<(BDIM * EDIM / 4) / 256, 256>>>(h, c, b_ih, b_hh);

    dim3 grid(G4 / BN, BDIM / BM);   // (16, 8) = 128 CTAs = 1 wave
    for (int t = 0; t < T; ++t)
        lstm_step<<<grid, NTHREADS, SMEM_LSTM>>>(t > 0 ? 1 : 0, t);

    dim3 opgrid(BDIM / OPR, T);
    dim3 opblk(17, 8);
    out_proj<<<opgrid, opblk, OPR * OPSTRIDE * 4>>>(W_out, b_out, out, T);
}

// round 10
// speedup vs baseline: 1.5661x; 1.5661x over previous
#include <cuda_runtime.h>
#include <cuda_bf16.h>
#include <cstdint>

#define EDIM 1024
#define BDIM 1024
#define G4   4096
#define MAXT 16
#define OUTD 34

#define BM 128
#define BN 256
#define BK 64
#define NCK (EDIM / BK)        // 16 k-chunks
#define NTHREADS 512

#define STAGEB 98304           // Ahi16K + Alo16K + Bhi32K + Blo32K
#define AHI 0
#define ALO 16384
#define BHI 32768
#define BLO 65536
#define SMEM_LSTM (1024 + 2 * STAGEB)   // bias + 2 stages = 197632

#define HSZ (BDIM * EDIM)

// ----------------- device scratch -----------------
__device__ __nv_bfloat16 g_Ws_hi[G4 * EDIM];
__device__ __nv_bfloat16 g_Ws_lo[G4 * EDIM];
__device__ __nv_bfloat16 g_Wh_hi[G4 * EDIM];
__device__ __nv_bfloat16 g_Wh_lo[G4 * EDIM];
__device__ float         g_bsum_p[G4];
// ping-pong h buffers: step t reads parity t&1, writes parity (t+1)&1.
__device__ __nv_bfloat16 g_hhi[2 * HSZ];
__device__ __nv_bfloat16 g_hlo[2 * HSZ];
__device__ float         g_c[HSZ];
__device__ float         g_hseq[MAXT * HSZ];

// ----------------- helpers -----------------
__device__ __forceinline__ uint32_t smem_u32(const void* p) {
    uint32_t a;
    asm("{ .reg .u64 t; cvta.to.shared.u64 t, %1; cvt.u32.u64 %0, t; }" : "=r"(a) : "l"(p));
    return a;
}
__device__ __forceinline__ void cpa16(uint32_t dst, const void* src) {
    asm volatile("cp.async.cg.shared.global [%0], [%1], 16;" :: "r"(dst), "l"(src));
}
__device__ __forceinline__ void cpa_commit() {
    asm volatile("cp.async.commit_group;" ::: "memory");
}
__device__ __forceinline__ void ldsm4(uint32_t* r, uint32_t a) {
    asm volatile("ldmatrix.sync.aligned.m8n8.x4.shared.b16 {%0,%1,%2,%3}, [%4];"
                 : "=r"(r[0]), "=r"(r[1]), "=r"(r[2]), "=r"(r[3]) : "r"(a));
}
__device__ __forceinline__ void mma16816(float* d,
                                         const uint32_t* a,
                                         uint32_t b0, uint32_t b1) {
    asm volatile("mma.sync.aligned.m16n8k16.row.col.f32.bf16.bf16.f32 "
                 "{%0,%1,%2,%3}, {%4,%5,%6,%7}, {%8,%9}, {%0,%1,%2,%3};"
                 : "+f"(d[0]), "+f"(d[1]), "+f"(d[2]), "+f"(d[3])
                 : "r"(a[0]), "r"(a[1]), "r"(a[2]), "r"(a[3]), "r"(b0), "r"(b1));
}
__device__ __forceinline__ float fsig(float x) {
    float t = __expf(-x);
    return __fdividef(1.f, 1.f + t);
}
__device__ __forceinline__ float ftanh_(float x) {
    float t = __expf(-2.f * x);
    return __fdividef(1.f - t, 1.f + t);
}
__device__ __forceinline__ void bsplit(float v, unsigned short& h, unsigned short& l) {
    __nv_bfloat16 hb = __float2bfloat16(v);
    float r = v - __bfloat162float(hb);
    __nv_bfloat16 lb = __float2bfloat16(r);
    h = __bfloat16_as_ushort(hb);
    l = __bfloat16_as_ushort(lb);
}

// permutation: original W row r = g*1024 + e  ->  rp = (e>>6)*256 + g*64 + (e&63)
// so N-block nb (256 rows) holds e in [nb*64, nb*64+64) for all 4 gates,
// gate g at local rows [g*64, g*64+64).

// ----------------- prep kernels -----------------
__global__ void prep_w(const float* __restrict__ Wih, const float* __restrict__ Whh) {
    int id = blockIdx.x * 256 + threadIdx.x;
    int r = id >> 8;
    int q = id & 255;
    float4 a = reinterpret_cast<const float4*>(Wih)[(size_t)r * 256 + q];
    float4 b = reinterpret_cast<const float4*>(Whh)[(size_t)r * 256 + q];
    int g = r >> 10, e = r & 1023;
    int rp = ((e >> 6) << 8) + (g << 6) + (e & 63);
    size_t o = (size_t)rp * 256 + q;

    ushort4 hh, hl, sh, sl;
    bsplit(b.x, hh.x, hl.x); bsplit(b.y, hh.y, hl.y);
    bsplit(b.z, hh.z, hl.z); bsplit(b.w, hh.w, hl.w);
    float4 s = make_float4(a.x + b.x, a.y + b.y, a.z + b.z, a.w + b.w);
    bsplit(s.x, sh.x, sl.x); bsplit(s.y, sh.y, sl.y);
    bsplit(s.z, sh.z, sl.z); bsplit(s.w, sh.w, sl.w);

    reinterpret_cast<ushort4*>(g_Wh_hi)[o] = hh;
    reinterpret_cast<ushort4*>(g_Wh_lo)[o] = hl;
    reinterpret_cast<ushort4*>(g_Ws_hi)[o] = sh;
    reinterpret_cast<ushort4*>(g_Ws_lo)[o] = sl;
}

__global__ void prep_state(const float* __restrict__ h0, const float* __restrict__ c0,
                           const float* __restrict__ bih, const float* __restrict__ bhh) {
    int id = blockIdx.x * 256 + threadIdx.x;
    float4 hv = reinterpret_cast<const float4*>(h0)[id];
    ushort4 hh, hl;
    bsplit(hv.x, hh.x, hl.x); bsplit(hv.y, hh.y, hl.y);
    bsplit(hv.z, hh.z, hl.z); bsplit(hv.w, hh.w, hl.w);
    reinterpret_cast<ushort4*>(g_hhi)[id] = hh;
    reinterpret_cast<ushort4*>(g_hlo)[id] = hl;
    reinterpret_cast<float4*>(g_c)[id] = reinterpret_cast<const float4*>(c0)[id];
    if (id < G4) {
        int g = id >> 10, e = id & 1023;
        int rp = ((e >> 6) << 8) + (g << 6) + (e & 63);
        g_bsum_p[rp] = bih[id] + bhh[id];
    }
}

// ----------------- fused GEMM (mma.sync bf16 3-term) + LSTM update -----------------
__global__ __launch_bounds__(NTHREADS, 1)
void lstm_step(int use_sum, int t) {
    extern __shared__ char smem[];
    float* bias_sm = reinterpret_cast<float*>(smem);
    const uint32_t sbase = smem_u32(smem) + 1024;
    const int tid = threadIdx.x;
    const int lane = tid & 31;
    const int w = tid >> 5;        // 0..15
    const int wm = w & 3;          // m-group (32 rows)
    const int we = w >> 2;         // e-group (16 e-cols)
    const int nb = blockIdx.x;     // 0..15
    const int mb = blockIdx.y;     // 0..7
    const int m0 = mb * BM, n0 = nb * BN;

    // ping-pong: read parity t&1, write parity (t+1)&1
    const __nv_bfloat16* __restrict__ hin_hi = g_hhi + (size_t)(t & 1) * HSZ;
    const __nv_bfloat16* __restrict__ hin_lo = g_hlo + (size_t)(t & 1) * HSZ;
    __nv_bfloat16* __restrict__ hout_hi = g_hhi + (size_t)((t + 1) & 1) * HSZ;
    __nv_bfloat16* __restrict__ hout_lo = g_hlo + (size_t)((t + 1) & 1) * HSZ;

    const __nv_bfloat16* __restrict__ Bh = use_sum ? g_Ws_hi : g_Wh_hi;
    const __nv_bfloat16* __restrict__ Bl = use_sum ? g_Ws_lo : g_Wh_lo;

    if (tid < BN) bias_sm[tid] = g_bsum_p[n0 + tid];

    // ---- loaders: 12 cp.async per thread per stage (512 threads) ----
    const int lrow = tid >> 3;     // 0..63
    const int lq = tid & 7;

#define LOAD_STAGE(s, kc)                                                          \
    {                                                                              \
        uint32_t sb = sbase + (s) * STAGEB;                                        \
        size_t gc = (size_t)(kc) * 64 + lq * 8;                                    \
        _Pragma("unroll")                                                          \
        for (int i = 0; i < 2; ++i) {                                              \
            int row = lrow + i * 64;                                               \
            uint32_t sf = (uint32_t)row * 128 + (((lq ^ (row & 7)) << 4));         \
            cpa16(sb + AHI + sf, hin_hi + (size_t)(m0 + row) * EDIM + gc);         \
            cpa16(sb + ALO + sf, hin_lo + (size_t)(m0 + row) * EDIM + gc);         \
        }                                                                          \
        _Pragma("unroll")                                                          \
        for (int i = 0; i < 4; ++i) {                                              \
            int row = lrow + i * 64;                                               \
            uint32_t sf = (uint32_t)row * 128 + (((lq ^ (row & 7)) << 4));         \
            cpa16(sb + BHI + sf, Bh + (size_t)(n0 + row) * EDIM + gc);             \
            cpa16(sb + BLO + sf, Bl + (size_t)(n0 + row) * EDIM + gc);             \
        }                                                                          \
        cpa_commit();                                                              \
    }

    // acc[mt][gate][sub][4] : m-tile mt (16 rows), gate, n8 sub-tile
    float acc[2][4][2][4];
#pragma unroll
    for (int i = 0; i < 2; ++i)
#pragma unroll
        for (int j = 0; j < 4; ++j)
#pragma unroll
            for (int s = 0; s < 2; ++s)
#pragma unroll
                for (int k = 0; k < 4; ++k) acc[i][j][s][k] = 0.f;

    // ldmatrix lane geometry
    const int arl = (lane & 7) + ((lane >> 3) & 1) * 8;   // A row within m16
    const int adq = lane >> 4;                            // A k-quad offset
    const int bn = (lane & 7) + ((lane >> 4) << 3);       // B n within n16
    const int bdq = (lane >> 3) & 1;                      // B k-quad offset

    // prologue: chunk 0 only (single group in flight)
    LOAD_STAGE(0, 0)

    for (int kc = 0; kc < NCK; ++kc) {
        asm volatile("cp.async.wait_group 0;" ::: "memory");  // chunk kc resident
        __syncthreads();          // visible to all; stage (kc+1)&1 free (all done kc-1)
        if (kc + 1 < NCK) {
            LOAD_STAGE((kc + 1) & 1, kc + 1)                  // overlaps compute below
        }

        uint32_t sb = sbase + (kc & 1) * STAGEB;
#pragma unroll
        for (int k16 = 0; k16 < 4; ++k16) {
            int qa = k16 * 2 + adq;
            int qb = k16 * 2 + bdq;
            uint32_t aoffs[2], boffs[4];
#pragma unroll
            for (int mt = 0; mt < 2; ++mt) {
                int ar = wm * 32 + mt * 16 + arl;
                aoffs[mt] = (uint32_t)ar * 128 + ((qa ^ (ar & 7)) << 4);
            }
#pragma unroll
            for (int g = 0; g < 4; ++g) {
                int br = g * 64 + we * 16 + bn;
                boffs[g] = (uint32_t)br * 128 + ((qb ^ (br & 7)) << 4);
            }
            uint32_t ah[2][4], bf[4][4];
#pragma unroll
            for (int mt = 0; mt < 2; ++mt) ldsm4(ah[mt], sb + AHI + aoffs[mt]);
#pragma unroll
            for (int g = 0; g < 4; ++g) ldsm4(bf[g], sb + BHI + boffs[g]);
            // pass 1: hi*hi
#pragma unroll
            for (int mt = 0; mt < 2; ++mt)
#pragma unroll
                for (int g = 0; g < 4; ++g) {
                    mma16816(acc[mt][g][0], ah[mt], bf[g][0], bf[g][1]);
                    mma16816(acc[mt][g][1], ah[mt], bf[g][2], bf[g][3]);
                }
            // pass 2: lo*hi (al live only here)
            {
                uint32_t al[2][4];
#pragma unroll
                for (int mt = 0; mt < 2; ++mt) ldsm4(al[mt], sb + ALO + aoffs[mt]);
#pragma unroll
                for (int mt = 0; mt < 2; ++mt)
#pragma unroll
                    for (int g = 0; g < 4; ++g) {
                        mma16816(acc[mt][g][0], al[mt], bf[g][0], bf[g][1]);
                        mma16816(acc[mt][g][1], al[mt], bf[g][2], bf[g][3]);
                    }
            }
            // pass 3: hi*lo (reuse bf registers for BLO fragments)
#pragma unroll
            for (int g = 0; g < 4; ++g) ldsm4(bf[g], sb + BLO + boffs[g]);
#pragma unroll
            for (int mt = 0; mt < 2; ++mt)
#pragma unroll
                for (int g = 0; g < 4; ++g) {
                    mma16816(acc[mt][g][0], ah[mt], bf[g][0], bf[g][1]);
                    mma16816(acc[mt][g][1], ah[mt], bf[g][2], bf[g][3]);
                }
        }
    }

    // ---- fused epilogue: per-thread register LSTM update ----
    const int mbase = m0 + wm * 32 + (lane >> 2);
    const int cp2 = (lane & 3) * 2;
    float* hseq = g_hseq + (size_t)t * HSZ;
#pragma unroll
    for (int mt = 0; mt < 2; ++mt) {
#pragma unroll
        for (int rr = 0; rr < 2; ++rr) {
            int m = mbase + mt * 16 + rr * 8;
#pragma unroll
            for (int sub = 0; sub < 2; ++sub) {
                int el = we * 16 + sub * 8 + cp2;
                float xi0 = acc[mt][0][sub][rr*2+0] + bias_sm[el];
                float xi1 = acc[mt][0][sub][rr*2+1] + bias_sm[el + 1];
                float xf0 = acc[mt][1][sub][rr*2+0] + bias_sm[64 + el];
                float xf1 = acc[mt][1][sub][rr*2+1] + bias_sm[64 + el + 1];
                float xg0 = acc[mt][2][sub][rr*2+0] + bias_sm[128 + el];
                float xg1 = acc[mt][2][sub][rr*2+1] + bias_sm[128 + el + 1];
                float xo0 = acc[mt][3][sub][rr*2+0] + bias_sm[192 + el];
                float xo1 = acc[mt][3][sub][rr*2+1] + bias_sm[192 + el + 1];
                size_t off = (size_t)m * EDIM + nb * 64 + el;
                float2 cold = *reinterpret_cast<const float2*>(g_c + off);
                float cn0 = fsig(xf0) * cold.x + fsig(xi0) * ftanh_(xg0);
                float cn1 = fsig(xf1) * cold.y + fsig(xi1) * ftanh_(xg1);
                float hn0 = fsig(xo0) * ftanh_(cn0);
                float hn1 = fsig(xo1) * ftanh_(cn1);
                *reinterpret_cast<float2*>(g_c + off) = make_float2(cn0, cn1);
                *reinterpret_cast<float2*>(hseq + off) = make_float2(hn0, hn1);
                unsigned short h0, l0, h1, l1;
                bsplit(hn0, h0, l0);
                bsplit(hn1, h1, l1);
                *reinterpret_cast<uint32_t*>(reinterpret_cast<unsigned short*>(hout_hi) + off) =
                    (uint32_t)h0 | ((uint32_t)h1 << 16);
                *reinterpret_cast<uint32_t*>(reinterpret_cast<unsigned short*>(hout_lo) + off) =
                    (uint32_t)l0 | ((uint32_t)l1 << 16);
            }
        }
    }
}

// ----------------- output projection -----------------
#define OPR 16
#define OPSTRIDE 1040
__global__ void out_proj(const float* __restrict__ Wo, const float* __restrict__ bo,
                         float* __restrict__ out, int T) {
    extern __shared__ float hs[];
    int t = blockIdx.y;
    int b0 = blockIdx.x * OPR;
    int tid = threadIdx.y * 17 + threadIdx.x;
    const float4* src = reinterpret_cast<const float4*>(g_hseq + ((size_t)t * BDIM + b0) * EDIM);
    for (int i = tid; i < OPR * 256; i += 136) {
        int r = i >> 8, c = i & 255;
        reinterpret_cast<float4*>(hs + r * OPSTRIDE)[c] = src[(size_t)r * 256 + c];
    }
    __syncthreads();
    int o0 = threadIdx.x * 2, o1 = o0 + 1;
    int r0 = threadIdx.y * 2, r1 = r0 + 1;
    const float4* w0 = reinterpret_cast<const float4*>(Wo + (size_t)o0 * EDIM);
    const float4* w1 = reinterpret_cast<const float4*>(Wo + (size_t)o1 * EDIM);
    const float4* h0 = reinterpret_cast<const float4*>(hs + r0 * OPSTRIDE);
    const float4* h1 = reinterpret_cast<const float4*>(hs + r1 * OPSTRIDE);
    float s00 = 0.f, s01 = 0.f, s10 = 0.f, s11 = 0.f;
#pragma unroll 4
    for (int k = 0; k < 256; ++k) {
        float4 a = h0[k], b = h1[k], x = w0[k], y = w1[k];
        s00 += a.x * x.x + a.y * x.y + a.z * x.z + a.w * x.w;
        s01 += a.x * y.x + a.y * y.y + a.z * y.z + a.w * y.w;
        s10 += b.x * x.x + b.y * x.y + b.z * x.z + b.w * x.w;
        s11 += b.x * y.x + b.y * y.y + b.z * y.z + b.w * y.w;
    }
    float bb0 = bo[o0], bb1 = bo[o1];
    size_t ob = ((size_t)(b0 + r0) * T + t) * OUTD;
    out[ob + o0] = s00 + bb0;
    out[ob + o1] = s01 + bb1;
    ob = ((size_t)(b0 + r1) * T + t) * OUTD;
    out[ob + o0] = s10 + bb0;
    out[ob + o1] = s11 + bb1;
}

// ----------------- launch -----------------
extern "C" void kernel_launch(void* const* d_in, const int* in_sizes, int n_in,
                              void* d_out, int out_size) {
    const float* h     = (const float*)d_in[0];
    const float* c     = (const float*)d_in[1];
    const float* W_ih  = (const float*)d_in[2];
    const float* W_hh  = (const float*)d_in[3];
    const float* b_ih  = (const float*)d_in[4];
    const float* b_hh  = (const float*)d_in[5];
    const float* W_out = (const float*)d_in[6];
    const float* b_out = (const float*)d_in[7];
    float* out = (float*)d_out;

    int T = out_size / (BDIM * OUTD);
    if (T < 1) T = 1;
    if (T > MAXT) T = MAXT;

    cudaFuncSetAttribute(lstm_step, cudaFuncAttributeMaxDynamicSharedMemorySize, SMEM_LSTM);
    cudaFuncSetAttribute(out_proj, cudaFuncAttributeMaxDynamicSharedMemorySize,
                         OPR * OPSTRIDE * 4);

    prep_w<<<G4, 256>>>(W_ih, W_hh);
    prep_state<<<(BDIM * EDIM / 4) / 256, 256>>>(h, c, b_ih, b_hh);

    dim3 grid(G4 / BN, BDIM / BM);   // (16, 8) = 128 CTAs = 1 wave
    for (int t = 0; t < T; ++t)
        lstm_step<<<grid, NTHREADS, SMEM_LSTM>>>(t > 0 ? 1 : 0, t);

    dim3 opgrid(BDIM / OPR, T);
    dim3 opblk(17, 8);
    out_proj<<<opgrid, opblk, OPR * OPSTRIDE * 4>>>(W_out, b_out, out, T);
}